// round 17
// baseline (speedup 1.0000x reference)
#include <cuda_runtime.h>
#include <cuda_bf16.h>
#include <cstdint>

// EngramGating via mma.sync (HMMA fallback on sm_103), R17 = R15 (65.3us) +
//  (1) B frags paired lane-major -> 40 LDS.128 instead of 80 LDS.64
//  (2) exact PRMT truncation hi/lo split (fewer instr, exact residual)
//  (3) bias folded into accumulator init (removes 40 FADD/tile)

#define HC       4
#define TILE_M   16
#define THREADS  256
#define NWARPS   8
#define NBLOCKS  296            // 148 SMs * 2 blocks

// ---- dynamic smem layout (bytes) ----
// sB2: [sect(5)][c2(4)][mp(2)][j(4)][gID(8)] ulonglong2 = 1280 * 16 = 20480
#define OFF_SB    0
#define OFF_BK4   20480                           // 64 * 16 = 1024
#define OFF_GG    21504                           // 128 f = 512
#define OFF_BV4   22016                           // 16 * 16 = 256
#define OFF_ES    22272                           // 8 warps * 16*40*4 = 20480
#define OFF_Q     42752                           // 8 * 8704 = 69632
#define OFF_GATE  112384                          // 8 * 256 = 2048
#define SMEM_TOTAL 114432

__device__ __forceinline__ unsigned su32(const void* p) {
    return (unsigned)__cvta_generic_to_shared(p);
}
__device__ __forceinline__ void cp16(unsigned d, const void* s) {
    asm volatile("cp.async.cg.shared.global [%0], [%1], 16;" :: "r"(d), "l"(s));
}
#define CP_COMMIT() asm volatile("cp.async.commit_group;")
#define CP_WAIT1()  asm volatile("cp.async.wait_group 1;")

// exact truncation split: hi = top 16 bits of each f32 (bf16), lo = f - hi (exact)
__device__ __forceinline__ unsigned packhi_t(float2 p) {
    return __byte_perm(__float_as_uint(p.x), __float_as_uint(p.y), 0x7632);
}
__device__ __forceinline__ unsigned packlo_t(float2 p) {
    float hx = __uint_as_float(__float_as_uint(p.x) & 0xFFFF0000u);
    float hy = __uint_as_float(__float_as_uint(p.y) & 0xFFFF0000u);
    __nv_bfloat162 l = __floats2bfloat162_rn(p.x - hx, p.y - hy);
    return *(unsigned*)&l;
}
__device__ __forceinline__ void mma_bf16(float4& d, const unsigned* a,
                                         unsigned b0, unsigned b1) {
    asm volatile(
        "mma.sync.aligned.m16n8k16.row.col.f32.bf16.bf16.f32 "
        "{%0,%1,%2,%3},{%4,%5,%6,%7},{%8,%9},{%0,%1,%2,%3};"
        : "+f"(d.x), "+f"(d.y), "+f"(d.z), "+f"(d.w)
        : "r"(a[0]), "r"(a[1]), "r"(a[2]), "r"(a[3]), "r"(b0), "r"(b1));
}
#define MMA_U64(acc, A, bu) \
    mma_bf16(acc, A, (unsigned)(bu), (unsigned)((bu) >> 32))

__global__ void __launch_bounds__(THREADS, 2)
engram_gating_mma(const float* __restrict__ emb,      // [T,32]
                  const float* __restrict__ hid,      // [T,4,32]
                  const float* __restrict__ Wv,       // [32,32]
                  const float* __restrict__ bv,       // [32]
                  const float* __restrict__ Wk,       // [4,32,32]
                  const float* __restrict__ bk,       // [4,32]
                  const float* __restrict__ g1,       // [4,32]
                  const float* __restrict__ g2,       // [4,32]
                  float* __restrict__ out,            // [T,4,32]
                  int nTok) {
    extern __shared__ __align__(16) char sm[];
    float* sGG = (float*)(sm + OFF_GG);

    const int tid = threadIdx.x;
    const int w = tid >> 5;
    const int lane = tid & 31;
    const int j = lane & 3;            // fragment quad-lane
    const int gID = lane >> 2;         // fragment group (0..7)
    const int r1 = gID, r2 = gID + 8;  // token rows covered by this thread

    // ---- weight prep: paired bf16 fragment layout ----
    // entry i: n = i%160, rr = i/160 = (bt*2+kt)*4 + jj
    for (int i = tid; i < 2560; i += THREADS) {
        int n = i % 160, rr = i / 160;
        int jj = rr & 3, c2 = rr >> 2;            // c2 = bt*2+kt
        int kt = c2 & 1;
        int d0 = kt * 16 + 2 * jj;
        const float* wr = (n < 128) ? (Wk + n * 32) : (Wv + (n - 128) * 32);
        float2 pa = make_float2(wr[d0], wr[d0 + 1]);
        float2 pb = make_float2(wr[d0 + 8], wr[d0 + 9]);
        unsigned lo32, hi32;
        if (c2 < 2) { lo32 = packhi_t(pa); hi32 = packhi_t(pb); }   // Whi rows
        else        { lo32 = packlo_t(pa); hi32 = packlo_t(pb); }   // Wlo rows
        unsigned long long frag = ((unsigned long long)hi32 << 32) | lo32;
        // destination: sect s, m, g8 within section
        int s  = (n < 128) ? (n >> 5) : 4;
        int nn = (n < 128) ? (n & 31) : (n - 128);
        int m = nn >> 3, g8 = nn & 7;
        int idx = ((((s * 4 + c2) * 2 + (m >> 1)) * 4 + jj) * 8 + g8);
        *(unsigned long long*)(sm + OFF_SB + idx * 16 + (m & 1) * 8) = frag;
    }
    // bias tables {b[c], b[c+1], b[c], b[c+1]} ; c = (h*32+) 2*j + 8*m
    for (int i = tid; i < 64; i += THREADS) {
        int h = i >> 4, j4 = (i >> 2) & 3, m = i & 3;
        int c = h * 32 + 2 * j4 + 8 * m;
        *(float4*)(sm + OFF_BK4 + i * 16) = make_float4(bk[c], bk[c+1], bk[c], bk[c+1]);
    }
    for (int i = tid; i < 16; i += THREADS) {
        int j4 = i >> 2, m = i & 3;
        int c = 2 * j4 + 8 * m;
        *(float4*)(sm + OFF_BV4 + i * 16) = make_float4(bv[c], bv[c+1], bv[c], bv[c+1]);
    }
    for (int i = tid; i < 128; i += THREADS) sGG[i] = g1[i] * g2[i];
    __syncthreads();

    float* esf = (float*)(sm + OFF_ES) + w * 640;      // e stage, stride 40 f
    float* sQf = (float*)(sm + OFF_Q) + w * 2176;      // q stage, stride 136 f
    float* sV  = sQf;                                  // value stage (q dead), stride 36 f
    float* sGate = (float*)(sm + OFF_GATE) + w * 64;   // [r][h]
    const unsigned qA = su32(sQf);
    const unsigned eA = su32(esf);
    const char* pB = sm + OFF_SB + j * 128 + gID * 16; // lane B base

    const int warpG = blockIdx.x * NWARPS + w;
    const int totW = NBLOCKS * NWARPS;
    const int nTiles = (nTok + TILE_M - 1) / TILE_M;

    const float EPS = 1.1920929e-07f;
    const float INV32 = 0.03125f;
    const float INVSQRT32 = 0.17677669529663687f;

    auto issue_e = [&](int g) {
        const int t0 = g * TILE_M;
        if (t0 + TILE_M <= nTok) {
            const char* ebase = (const char*)(emb + (size_t)t0 * 32);
#pragma unroll
            for (int it = 0; it < 4; it++) {
                int f = it * 32 + lane;
                cp16(eA + (f >> 3) * 160 + (f & 7) * 16, ebase + f * 16);
            }
        } else {
#pragma unroll
            for (int it = 0; it < 4; it++) {
                int f = it * 32 + lane;
                int row = min(t0 + (f >> 3), nTok - 1);
                cp16(eA + (f >> 3) * 160 + (f & 7) * 16,
                     (const char*)(emb + (size_t)row * 32 + (f & 7) * 4));
            }
        }
    };

    // ---- prologue: stage e for first tile ----
    if (warpG < nTiles) issue_e(warpG);
    CP_COMMIT();

    for (int g = warpG; g < nTiles; g += totW) {
        const int t0 = g * TILE_M;
        const bool full = (t0 + TILE_M) <= nTok;

        // ---- 1. q -> smem via cp.async ; pending {E_g, Q_g} ----
        if (full) {
            const char* hbase = (const char*)(hid + (size_t)t0 * 128);
#pragma unroll
            for (int it = 0; it < 16; it++)
                cp16(qA + it * 544 + lane * 16, hbase + it * 512 + lane * 16);
        } else {
#pragma unroll
            for (int it = 0; it < 16; it++) {
                int row = min(t0 + it, nTok - 1);
                cp16(qA + it * 544 + lane * 16,
                     (const char*)(hid + (size_t)row * 128 + lane * 4));
            }
        }
        CP_COMMIT();

        // ---- 2. wait for e ----
        CP_WAIT1();

        // ---- 3. A fragments (exact hi/lo split) ----
        unsigned Ahi[2][4], Alo[2][4];
#pragma unroll
        for (int kt = 0; kt < 2; kt++) {
            int c0 = 16 * kt + 2 * j;
            float2 p0 = *(const float2*)(esf + r1 * 40 + c0);
            float2 p1 = *(const float2*)(esf + r2 * 40 + c0);
            float2 p2 = *(const float2*)(esf + r1 * 40 + c0 + 8);
            float2 p3 = *(const float2*)(esf + r2 * 40 + c0 + 8);
            Ahi[kt][0] = packhi_t(p0); Alo[kt][0] = packlo_t(p0);
            Ahi[kt][1] = packhi_t(p1); Alo[kt][1] = packlo_t(p1);
            Ahi[kt][2] = packhi_t(p2); Alo[kt][2] = packlo_t(p2);
            Ahi[kt][3] = packhi_t(p3); Alo[kt][3] = packlo_t(p3);
        }
        if (!full) {
#pragma unroll
            for (int kt = 0; kt < 2; kt++) {
                if (t0 + r1 >= nTok) { Ahi[kt][0] = Alo[kt][0] = 0u;
                                       Ahi[kt][2] = Alo[kt][2] = 0u; }
                if (t0 + r2 >= nTok) { Ahi[kt][1] = Alo[kt][1] = 0u;
                                       Ahi[kt][3] = Alo[kt][3] = 0u; }
            }
        }

        // ---- 4. stage e for NEXT tile ; pending {Q_g, E_next} ----
        {
            int gn = g + totW;
            if (gn < nTiles) issue_e(gn);
            CP_COMMIT();
        }

        // ---- 5. value MMAs (sect 4): bias-init acc, paired B loads ----
        float4 accV[4];
#pragma unroll
        for (int m = 0; m < 4; m++)
            accV[m] = *(const float4*)(sm + OFF_BV4 + (j * 4 + m) * 16);
#pragma unroll
        for (int kt = 0; kt < 2; kt++) {           // Whi rows: shared Ahi+Alo
            const char* bp = pB + (16 + kt) * 1024;
            ulonglong2 bb0 = *(const ulonglong2*)bp;
            ulonglong2 bb1 = *(const ulonglong2*)(bp + 512);
            MMA_U64(accV[0], Ahi[kt], bb0.x);
            MMA_U64(accV[1], Ahi[kt], bb0.y);
            MMA_U64(accV[2], Ahi[kt], bb1.x);
            MMA_U64(accV[3], Ahi[kt], bb1.y);
            MMA_U64(accV[0], Alo[kt], bb0.x);
            MMA_U64(accV[1], Alo[kt], bb0.y);
            MMA_U64(accV[2], Alo[kt], bb1.x);
            MMA_U64(accV[3], Alo[kt], bb1.y);
        }
#pragma unroll
        for (int kt = 0; kt < 2; kt++) {           // Wlo rows x Ahi
            const char* bp = pB + (18 + kt) * 1024;
            ulonglong2 bb0 = *(const ulonglong2*)bp;
            ulonglong2 bb1 = *(const ulonglong2*)(bp + 512);
            MMA_U64(accV[0], Ahi[kt], bb0.x);
            MMA_U64(accV[1], Ahi[kt], bb0.y);
            MMA_U64(accV[2], Ahi[kt], bb1.x);
            MMA_U64(accV[3], Ahi[kt], bb1.y);
        }

        // ---- 6. q ready ----
        CP_WAIT1();

        // ---- 7. heads: key MMAs + gate epilogue ----
#pragma unroll 1
        for (int h = 0; h < HC; h++) {
            float4 accK[4];
#pragma unroll
            for (int m = 0; m < 4; m++)
                accK[m] = *(const float4*)(sm + OFF_BK4 + h * 256 + (j * 4 + m) * 16);
#pragma unroll
            for (int kt = 0; kt < 2; kt++) {       // Whi shared
                const char* bp = pB + (h * 4 + kt) * 1024;
                ulonglong2 bb0 = *(const ulonglong2*)bp;
                ulonglong2 bb1 = *(const ulonglong2*)(bp + 512);
                MMA_U64(accK[0], Ahi[kt], bb0.x);
                MMA_U64(accK[1], Ahi[kt], bb0.y);
                MMA_U64(accK[2], Ahi[kt], bb1.x);
                MMA_U64(accK[3], Ahi[kt], bb1.y);
                MMA_U64(accK[0], Alo[kt], bb0.x);
                MMA_U64(accK[1], Alo[kt], bb0.y);
                MMA_U64(accK[2], Alo[kt], bb1.x);
                MMA_U64(accK[3], Alo[kt], bb1.y);
            }
#pragma unroll
            for (int kt = 0; kt < 2; kt++) {       // Wlo x Ahi
                const char* bp = pB + (h * 4 + 2 + kt) * 1024;
                ulonglong2 bb0 = *(const ulonglong2*)bp;
                ulonglong2 bb1 = *(const ulonglong2*)(bp + 512);
                MMA_U64(accK[0], Ahi[kt], bb0.x);
                MMA_U64(accK[1], Ahi[kt], bb0.y);
                MMA_U64(accK[2], Ahi[kt], bb1.x);
                MMA_U64(accK[3], Ahi[kt], bb1.y);
            }

            const float* ggh = sGG + h * 32 + 2 * j;
            const float* q1p = sQf + r1 * 136 + h * 32 + 2 * j;
            const float* q2p = sQf + r2 * 136 + h * 32 + 2 * j;

            float kk1 = 0.f, qq1 = 0.f, kq1 = 0.f;
            float kk2 = 0.f, qq2 = 0.f, kq2 = 0.f;
#pragma unroll
            for (int m = 0; m < 4; m++) {
                float2 ggp = *(const float2*)(ggh + 8 * m);
                float2 q1 = *(const float2*)(q1p + 8 * m);
                float2 q2 = *(const float2*)(q2p + 8 * m);
                float k0 = accK[m].x, k1 = accK[m].y;   // row r1 (bias pre-added)
                float k2 = accK[m].z, k3 = accK[m].w;   // row r2
                kk1 += k0 * k0 + k1 * k1;
                kk2 += k2 * k2 + k3 * k3;
                qq1 += q1.x * q1.x + q1.y * q1.y;
                qq2 += q2.x * q2.x + q2.y * q2.y;
                kq1 += k0 * ggp.x * q1.x + k1 * ggp.y * q1.y;
                kq2 += k2 * ggp.x * q2.x + k3 * ggp.y * q2.y;
            }
#pragma unroll
            for (int msk = 1; msk < 4; msk <<= 1) {
                kk1 += __shfl_xor_sync(0xffffffffu, kk1, msk);
                qq1 += __shfl_xor_sync(0xffffffffu, qq1, msk);
                kq1 += __shfl_xor_sync(0xffffffffu, kq1, msk);
                kk2 += __shfl_xor_sync(0xffffffffu, kk2, msk);
                qq2 += __shfl_xor_sync(0xffffffffu, qq2, msk);
                kq2 += __shfl_xor_sync(0xffffffffu, kq2, msk);
            }
            float rA = kq1 * rsqrtf(fmaf(kk1, INV32, EPS))
                           * rsqrtf(fmaf(qq1, INV32, EPS)) * INVSQRT32;
            float rB = kq2 * rsqrtf(fmaf(kk2, INV32, EPS))
                           * rsqrtf(fmaf(qq2, INV32, EPS)) * INVSQRT32;
            float aA = sqrtf(fmaxf(fabsf(rA), 1e-6f));
            aA = (rA > 0.f) ? aA : ((rA < 0.f) ? -aA : 0.f);
            float aB = sqrtf(fmaxf(fabsf(rB), 1e-6f));
            aB = (rB > 0.f) ? aB : ((rB < 0.f) ? -aB : 0.f);
            float gA = 1.0f / (1.0f + __expf(-aA));
            float gB = 1.0f / (1.0f + __expf(-aB));
            if (j == 0) {
                sGate[r1 * 4 + h] = gA;
                sGate[r2 * 4 + h] = gB;
            }
        }
        __syncwarp();

        // ---- 8. stage values (q buffer dead; stride 36 f), coalesced out ----
#pragma unroll
        for (int m = 0; m < 4; m++) {
            *(float2*)(sV + r1 * 36 + 8 * m + 2 * j) =
                make_float2(accV[m].x, accV[m].y);
            *(float2*)(sV + r2 * 36 + 8 * m + 2 * j) =
                make_float2(accV[m].z, accV[m].w);
        }
        __syncwarp();
        {
            const int hL = lane >> 3;          // head of this lane's out chunk
            const int k4 = lane & 7;           // 4-float span within head
#pragma unroll
            for (int it = 0; it < TILE_M; it++) {
                if (full || (t0 + it) < nTok) {
                    float4 v = *(const float4*)(sV + it * 36 + k4 * 4);
                    float gt = sGate[it * 4 + hL];
                    *(float4*)(out + (size_t)(t0 + it) * 128 + lane * 4) =
                        make_float4(gt * v.x, gt * v.y, gt * v.z, gt * v.w);
                }
            }
        }
        __syncwarp();
    }
}

extern "C" void kernel_launch(void* const* d_in, const int* in_sizes, int n_in,
                              void* d_out, int out_size) {
    const float* emb = (const float*)d_in[0];
    const float* hid = (const float*)d_in[1];
    const float* Wv  = (const float*)d_in[2];
    const float* bv  = (const float*)d_in[3];
    const float* Wk  = (const float*)d_in[4];
    const float* bk  = (const float*)d_in[5];
    const float* g1  = (const float*)d_in[6];
    const float* g2  = (const float*)d_in[7];
    float* out = (float*)d_out;

    int nTok = in_sizes[0] / 32;

    cudaFuncSetAttribute(engram_gating_mma,
                         cudaFuncAttributeMaxDynamicSharedMemorySize, SMEM_TOTAL);

    engram_gating_mma<<<NBLOCKS, THREADS, SMEM_TOTAL>>>(
        emb, hid, Wv, bv, Wk, bk, g1, g2, out, nTok);
}